// round 2
// baseline (speedup 1.0000x reference)
#include <cuda_runtime.h>
#include <math.h>

// ---------------- problem constants ----------------
#define B_   2
#define S_   2048
#define H_   2048
#define NH_  16
#define DH_  128
#define E_   6
#define R_   16
#define T_   (B_ * S_)            // 4096 tokens
#define SCALING_ 8.0f
#define INV_SQRT_DH 0.08838834764831845f

// ---------------- scratch (device globals; no allocation allowed) ----------------
__device__ float g_q[T_ * H_];
__device__ float g_k[T_ * H_];
__device__ float g_v[T_ * H_];
__device__ float g_ctx[T_ * H_];
__device__ float g_scores[(size_t)B_ * NH_ * S_ * S_];  // 537 MB
__device__ float g_xa_q[T_ * R_];
__device__ float g_xa_k[T_ * R_];
__device__ float g_xa_v[E_ * T_ * R_];
__device__ float g_xa_o[E_ * T_ * R_];
__device__ int   g_list_v[E_ * T_];
__device__ int   g_list_o[E_ * T_];
__device__ int   g_cnt_v[E_];
__device__ int   g_cnt_o[E_];
__device__ float g_wslot_v[T_ * 2];
__device__ float g_wslot_o[T_ * 2];

// ---------------- init: zero the routing counters (must reset every replay) ----------------
__global__ void init_counts_kernel() {
    if (threadIdx.x < E_) {
        g_cnt_v[threadIdx.x] = 0;
        g_cnt_o[threadIdx.x] = 0;
    }
}

// ---------------- routing: sigmoid gate, top-2, softmax weights, build gather lists ----------------
__global__ void routing_kernel(const float* __restrict__ x,
                               const float* __restrict__ gv,
                               const float* __restrict__ go) {
    int t = blockIdx.x;
    const float* xt = x + (size_t)t * H_;
    float pv[E_], po[E_];
#pragma unroll
    for (int e = 0; e < E_; e++) { pv[e] = 0.f; po[e] = 0.f; }
    for (int k = threadIdx.x; k < H_; k += 128) {
        float xv = xt[k];
#pragma unroll
        for (int e = 0; e < E_; e++) {
            pv[e] += xv * gv[e * H_ + k];
            po[e] += xv * go[e * H_ + k];
        }
    }
    __shared__ float red[2 * E_][128];
#pragma unroll
    for (int e = 0; e < E_; e++) {
        red[e][threadIdx.x] = pv[e];
        red[E_ + e][threadIdx.x] = po[e];
    }
    __syncthreads();
    if (threadIdx.x < 2 * E_) {
        float s = 0.f;
        for (int i = 0; i < 128; i++) s += red[threadIdx.x][i];
        red[threadIdx.x][0] = s;
    }
    __syncthreads();
    if (threadIdx.x < 2) {
        bool isO = (threadIdx.x == 1);
        float sc[E_];
#pragma unroll
        for (int e = 0; e < E_; e++) {
            float d = red[(isO ? E_ : 0) + e][0];
            sc[e] = 1.f / (1.f + expf(-d));
        }
        int e0 = 0;
        for (int e = 1; e < E_; e++) if (sc[e] > sc[e0]) e0 = e;
        int e1 = -1;
        for (int e = 0; e < E_; e++) {
            if (e == e0) continue;
            if (e1 < 0 || sc[e] > sc[e1]) e1 = e;
        }
        float t1 = expf(sc[e1] - sc[e0]);
        float w0 = 1.f / (1.f + t1);
        float w1 = t1 / (1.f + t1);
        if (!isO) {
            g_wslot_v[t * 2 + 0] = w0;
            g_wslot_v[t * 2 + 1] = w1;
            int p0 = atomicAdd(&g_cnt_v[e0], 1); g_list_v[e0 * T_ + p0] = t * 2 + 0;
            int p1 = atomicAdd(&g_cnt_v[e1], 1); g_list_v[e1 * T_ + p1] = t * 2 + 1;
        } else {
            g_wslot_o[t * 2 + 0] = w0;
            g_wslot_o[t * 2 + 1] = w1;
            int p0 = atomicAdd(&g_cnt_o[e0], 1); g_list_o[e0 * T_ + p0] = t * 2 + 0;
            int p1 = atomicAdd(&g_cnt_o[e1], 1); g_list_o[e1 * T_ + p1] = t * 2 + 1;
        }
    }
}

// ---------------- LoRA down-projection for q/k: xa = x @ a^T, [T,16] ----------------
__global__ void xa_qk_kernel(const float* __restrict__ x,
                             const float* __restrict__ qa,
                             const float* __restrict__ ka) {
    int t = blockIdx.x;
    const float* xt = x + (size_t)t * H_;
    float aq[R_], ak[R_];
#pragma unroll
    for (int r = 0; r < R_; r++) { aq[r] = 0.f; ak[r] = 0.f; }
    for (int k = threadIdx.x; k < H_; k += 256) {
        float xv = xt[k];
#pragma unroll
        for (int r = 0; r < R_; r++) {
            aq[r] += xv * qa[r * H_ + k];
            ak[r] += xv * ka[r * H_ + k];
        }
    }
    __shared__ float red[32][256];
#pragma unroll
    for (int r = 0; r < R_; r++) {
        red[r][threadIdx.x] = aq[r];
        red[R_ + r][threadIdx.x] = ak[r];
    }
    __syncthreads();
    if (threadIdx.x < 32) {
        float s = 0.f;
        for (int i = 0; i < 256; i++) s += red[threadIdx.x][i];
        if (threadIdx.x < R_) g_xa_q[t * R_ + threadIdx.x] = s;
        else                  g_xa_k[t * R_ + (threadIdx.x - R_)] = s;
    }
}

// ---------------- LoRA down-projection per expert: out[e,t,:] = inp[t] @ a[e]^T ----------------
__global__ void xa_moe_kernel(const float* __restrict__ inp,
                              const float* __restrict__ a,  // [E,R,H]
                              float* __restrict__ out) {    // [E,T,R]
    int t = blockIdx.x, e = blockIdx.y;
    const float* xt = inp + (size_t)t * H_;
    const float* ae = a + (size_t)e * R_ * H_;
    float ac[R_];
#pragma unroll
    for (int r = 0; r < R_; r++) ac[r] = 0.f;
    for (int k = threadIdx.x; k < H_; k += 256) {
        float xv = xt[k];
#pragma unroll
        for (int r = 0; r < R_; r++) ac[r] += xv * ae[r * H_ + k];
    }
    __shared__ float red[R_][256];
#pragma unroll
    for (int r = 0; r < R_; r++) red[r][threadIdx.x] = ac[r];
    __syncthreads();
    if (threadIdx.x < R_) {
        float s = 0.f;
        for (int i = 0; i < 256; i++) s += red[threadIdx.x][i];
        out[((size_t)e * T_ + t) * R_ + threadIdx.x] = s;
    }
}

// ================= SGEMM core macros (128x128 tile, TK=16, 256 threads, 8x8/thread) =================
#define SMEM_DECL  __shared__ float As[16][132]; __shared__ float Bs[16][132];

#define INNER_16() \
    _Pragma("unroll") \
    for (int kk = 0; kk < 16; kk++) { \
        float4 av0 = *(const float4*)&As[kk][ty * 4]; \
        float4 av1 = *(const float4*)&As[kk][ty * 4 + 64]; \
        float4 bv0 = *(const float4*)&Bs[kk][tx * 4]; \
        float4 bv1 = *(const float4*)&Bs[kk][tx * 4 + 64]; \
        float a[8] = {av0.x, av0.y, av0.z, av0.w, av1.x, av1.y, av1.z, av1.w}; \
        float b[8] = {bv0.x, bv0.y, bv0.z, bv0.w, bv1.x, bv1.y, bv1.z, bv1.w}; \
        _Pragma("unroll") \
        for (int i = 0; i < 8; i++) \
            _Pragma("unroll") \
            for (int j = 0; j < 8; j++) acc[i][j] += a[i] * b[j]; \
    }

// ---------------- proj GEMM: C = A @ W^T + SCALING * (La @ Lb^T) ----------------
// A:[T_,H_], W:[H_,H_] (N,K), La:[T_,R_], Lb:[H_,R_], C:[T_,H_]
__global__ void __launch_bounds__(256, 2) gemm_proj_kernel(
    const float* __restrict__ A, const float* __restrict__ W,
    const float* __restrict__ La, const float* __restrict__ Lb,
    float* __restrict__ C) {
    SMEM_DECL
    int tid = threadIdx.x;
    int tx = tid & 15, ty = tid >> 4;
    int m0 = blockIdx.y * 128, n0 = blockIdx.x * 128;
    float acc[8][8];
#pragma unroll
    for (int i = 0; i < 8; i++)
#pragma unroll
        for (int j = 0; j < 8; j++) acc[i][j] = 0.f;

    for (int kt = 0; kt < H_; kt += 16) {
#pragma unroll
        for (int i = 0; i < 2; i++) {
            int f = tid + i * 256;
            int row = f >> 2, kc = (f & 3) * 4;
            float4 va = *(const float4*)&A[(size_t)(m0 + row) * H_ + kt + kc];
            As[kc + 0][row] = va.x; As[kc + 1][row] = va.y; As[kc + 2][row] = va.z; As[kc + 3][row] = va.w;
            float4 vb = *(const float4*)&W[(size_t)(n0 + row) * H_ + kt + kc];
            Bs[kc + 0][row] = vb.x; Bs[kc + 1][row] = vb.y; Bs[kc + 2][row] = vb.z; Bs[kc + 3][row] = vb.w;
        }
        __syncthreads();
        INNER_16()
        __syncthreads();
    }
    // LoRA epilogue (16 extra k-steps, La pre-scaled by SCALING_)
#pragma unroll
    for (int i = 0; i < 2; i++) {
        int f = tid + i * 256;
        int row = f >> 2, kc = (f & 3) * 4;
        float4 va = *(const float4*)&La[(size_t)(m0 + row) * R_ + kc];
        As[kc + 0][row] = SCALING_ * va.x; As[kc + 1][row] = SCALING_ * va.y;
        As[kc + 2][row] = SCALING_ * va.z; As[kc + 3][row] = SCALING_ * va.w;
        float4 vb = *(const float4*)&Lb[(size_t)(n0 + row) * R_ + kc];
        Bs[kc + 0][row] = vb.x; Bs[kc + 1][row] = vb.y; Bs[kc + 2][row] = vb.z; Bs[kc + 3][row] = vb.w;
    }
    __syncthreads();
    INNER_16()

#pragma unroll
    for (int i = 0; i < 8; i++) {
        int r = m0 + ty * 4 + (i & 3) + ((i & 4) ? 64 : 0);
        float* crow = &C[(size_t)r * H_ + n0];
        float4 v0 = {acc[i][0], acc[i][1], acc[i][2], acc[i][3]};
        float4 v1 = {acc[i][4], acc[i][5], acc[i][6], acc[i][7]};
        *(float4*)&crow[tx * 4] = v0;
        *(float4*)&crow[tx * 4 + 64] = v1;
    }
}

// ---------------- gathered MoE GEMM: out[token] += w * (X[token] @ Wb[e]^T + SCALING*(xa[e,token] @ Lb[e]^T)) ----------------
__global__ void __launch_bounds__(256, 2) gemm_moe_kernel(
    const float* __restrict__ X,     // [T_,H_]
    const float* __restrict__ Wbase, // [E_,H_,H_]
    const float* __restrict__ Lbf,   // [E_,H_,R_]
    const float* __restrict__ xa,    // [E_,T_,R_]
    const int* __restrict__ list, const int* __restrict__ cnt,
    const float* __restrict__ wslot,
    float* __restrict__ Out) {
    int e = blockIdx.z;
    int count = cnt[e];
    int m0 = blockIdx.y * 128;
    if (m0 >= count) return;
    __shared__ int esm[128];
    __shared__ int tok[128];
    SMEM_DECL
    int tid = threadIdx.x;
    int tx = tid & 15, ty = tid >> 4;
    int n0 = blockIdx.x * 128;
    if (tid < 128) {
        int idx = m0 + tid;
        int en = (idx < count) ? list[e * T_ + idx] : -1;
        esm[tid] = en;
        tok[tid] = (en >= 0) ? (en >> 1) : 0;
    }
    __syncthreads();
    const float* W  = Wbase + (size_t)e * H_ * H_;
    const float* Lb = Lbf   + (size_t)e * H_ * R_;
    const float* La = xa    + (size_t)e * T_ * R_;

    float acc[8][8];
#pragma unroll
    for (int i = 0; i < 8; i++)
#pragma unroll
        for (int j = 0; j < 8; j++) acc[i][j] = 0.f;

    for (int kt = 0; kt < H_; kt += 16) {
#pragma unroll
        for (int i = 0; i < 2; i++) {
            int f = tid + i * 256;
            int row = f >> 2, kc = (f & 3) * 4;
            int token = tok[row];
            float4 va = *(const float4*)&X[(size_t)token * H_ + kt + kc];
            As[kc + 0][row] = va.x; As[kc + 1][row] = va.y; As[kc + 2][row] = va.z; As[kc + 3][row] = va.w;
            float4 vb = *(const float4*)&W[(size_t)(n0 + row) * H_ + kt + kc];
            Bs[kc + 0][row] = vb.x; Bs[kc + 1][row] = vb.y; Bs[kc + 2][row] = vb.z; Bs[kc + 3][row] = vb.w;
        }
        __syncthreads();
        INNER_16()
        __syncthreads();
    }
    // LoRA epilogue
#pragma unroll
    for (int i = 0; i < 2; i++) {
        int f = tid + i * 256;
        int row = f >> 2, kc = (f & 3) * 4;
        int token = tok[row];
        float4 va = *(const float4*)&La[(size_t)token * R_ + kc];
        As[kc + 0][row] = SCALING_ * va.x; As[kc + 1][row] = SCALING_ * va.y;
        As[kc + 2][row] = SCALING_ * va.z; As[kc + 3][row] = SCALING_ * va.w;
        float4 vb = *(const float4*)&Lb[(size_t)(n0 + row) * R_ + kc];
        Bs[kc + 0][row] = vb.x; Bs[kc + 1][row] = vb.y; Bs[kc + 2][row] = vb.z; Bs[kc + 3][row] = vb.w;
    }
    __syncthreads();
    INNER_16()

#pragma unroll
    for (int i = 0; i < 8; i++) {
        int lr = ty * 4 + (i & 3) + ((i & 4) ? 64 : 0);
        int en = esm[lr];
        if (en < 0) continue;
        int token = en >> 1;
        float w = wslot[en];
        float* crow = &Out[(size_t)token * H_ + n0];
#pragma unroll
        for (int j = 0; j < 8; j++) {
            int col = tx * 4 + (j & 3) + ((j & 4) ? 64 : 0);
            atomicAdd(&crow[col], w * acc[i][j]);
        }
    }
}

// ---------------- batched scores: S[z] = (Qz @ Kz^T) / sqrt(DH) ----------------
__global__ void __launch_bounds__(256, 2) gemm_scores_kernel() {
    int z = blockIdx.z;
    int b = z / NH_, h = z % NH_;
    const float* A  = g_q + (size_t)b * S_ * H_ + h * DH_;
    const float* Bp = g_k + (size_t)b * S_ * H_ + h * DH_;
    float* C = g_scores + (size_t)z * S_ * S_;
    SMEM_DECL
    int tid = threadIdx.x;
    int tx = tid & 15, ty = tid >> 4;
    int m0 = blockIdx.y * 128, n0 = blockIdx.x * 128;
    float acc[8][8];
#pragma unroll
    for (int i = 0; i < 8; i++)
#pragma unroll
        for (int j = 0; j < 8; j++) acc[i][j] = 0.f;

    for (int kt = 0; kt < DH_; kt += 16) {
#pragma unroll
        for (int i = 0; i < 2; i++) {
            int f = tid + i * 256;
            int row = f >> 2, kc = (f & 3) * 4;
            float4 va = *(const float4*)&A[(size_t)(m0 + row) * H_ + kt + kc];
            As[kc + 0][row] = va.x; As[kc + 1][row] = va.y; As[kc + 2][row] = va.z; As[kc + 3][row] = va.w;
            float4 vb = *(const float4*)&Bp[(size_t)(n0 + row) * H_ + kt + kc];
            Bs[kc + 0][row] = vb.x; Bs[kc + 1][row] = vb.y; Bs[kc + 2][row] = vb.z; Bs[kc + 3][row] = vb.w;
        }
        __syncthreads();
        INNER_16()
        __syncthreads();
    }
#pragma unroll
    for (int i = 0; i < 8; i++) {
        int r = m0 + ty * 4 + (i & 3) + ((i & 4) ? 64 : 0);
        float* crow = &C[(size_t)r * S_ + n0];
        float4 v0 = {INV_SQRT_DH * acc[i][0], INV_SQRT_DH * acc[i][1],
                     INV_SQRT_DH * acc[i][2], INV_SQRT_DH * acc[i][3]};
        float4 v1 = {INV_SQRT_DH * acc[i][4], INV_SQRT_DH * acc[i][5],
                     INV_SQRT_DH * acc[i][6], INV_SQRT_DH * acc[i][7]};
        *(float4*)&crow[tx * 4] = v0;
        *(float4*)&crow[tx * 4 + 64] = v1;
    }
}

// ---------------- row softmax with additive mask, in-place on g_scores ----------------
__global__ void softmax_kernel(const float* __restrict__ amask) {
    size_t row = blockIdx.x;                 // 0 .. B*NH*S-1
    int b = (int)(row / ((size_t)NH_ * S_));
    float* p = g_scores + row * S_;
    const float* mk = amask + (size_t)b * S_;
    int tid = threadIdx.x;
    __shared__ float red[256];

    float mx = -1e30f;
    for (int k = tid; k < S_; k += 256) {
        float v = p[k] + (1.f - mk[k]) * (-10000.f);
        mx = fmaxf(mx, v);
    }
    red[tid] = mx;
    __syncthreads();
    for (int s = 128; s > 0; s >>= 1) {
        if (tid < s) red[tid] = fmaxf(red[tid], red[tid + s]);
        __syncthreads();
    }
    float MX = red[0];
    __syncthreads();

    float sum = 0.f;
    for (int k = tid; k < S_; k += 256) {
        float v = expf(p[k] + (1.f - mk[k]) * (-10000.f) - MX);
        p[k] = v;
        sum += v;
    }
    red[tid] = sum;
    __syncthreads();
    for (int s = 128; s > 0; s >>= 1) {
        if (tid < s) red[tid] += red[tid + s];
        __syncthreads();
    }
    float inv = 1.f / red[0];
    for (int k = tid; k < S_; k += 256) p[k] *= inv;
}

// ---------------- batched NN ctx GEMM: ctx[z] = P[z] @ V_head[z] ----------------
__global__ void __launch_bounds__(256, 2) gemm_ctx_kernel() {
    int z = blockIdx.z;
    int b = z / NH_, h = z % NH_;
    const float* P = g_scores + (size_t)z * S_ * S_;
    const float* V = g_v   + (size_t)b * S_ * H_ + h * DH_;
    float* C       = g_ctx + (size_t)b * S_ * H_ + h * DH_;
    SMEM_DECL
    int tid = threadIdx.x;
    int tx = tid & 15, ty = tid >> 4;
    int m0 = blockIdx.y * 128;   // gridDim.x == 1 (N = 128)
    float acc[8][8];
#pragma unroll
    for (int i = 0; i < 8; i++)
#pragma unroll
        for (int j = 0; j < 8; j++) acc[i][j] = 0.f;

    for (int kt = 0; kt < S_; kt += 16) {
#pragma unroll
        for (int i = 0; i < 2; i++) {
            int f = tid + i * 256;
            int row = f >> 2, kc = (f & 3) * 4;
            float4 va = *(const float4*)&P[(size_t)(m0 + row) * S_ + kt + kc];
            As[kc + 0][row] = va.x; As[kc + 1][row] = va.y; As[kc + 2][row] = va.z; As[kc + 3][row] = va.w;
            // direct (non-transposed) B load: Bs[k][n] = V[(kt+k)*H_ + n]
            int kr = f >> 5, nc = (f & 31) * 4;
            float4 vb = *(const float4*)&V[(size_t)(kt + kr) * H_ + nc];
            *(float4*)&Bs[kr][nc] = vb;
        }
        __syncthreads();
        INNER_16()
        __syncthreads();
    }
#pragma unroll
    for (int i = 0; i < 8; i++) {
        int r = m0 + ty * 4 + (i & 3) + ((i & 4) ? 64 : 0);
        float* crow = &C[(size_t)r * H_];
        float4 v0 = {acc[i][0], acc[i][1], acc[i][2], acc[i][3]};
        float4 v1 = {acc[i][4], acc[i][5], acc[i][6], acc[i][7]};
        *(float4*)&crow[tx * 4] = v0;
        *(float4*)&crow[tx * 4 + 64] = v1;
    }
}

// ---------------- launcher ----------------
extern "C" void kernel_launch(void* const* d_in, const int* in_sizes, int n_in,
                              void* d_out, int out_size) {
    const float* x      = (const float*)d_in[0];
    const float* amask  = (const float*)d_in[1];
    const float* wq     = (const float*)d_in[2];
    const float* wk     = (const float*)d_in[3];
    const float* q_a    = (const float*)d_in[4];
    const float* q_b    = (const float*)d_in[5];
    const float* k_a    = (const float*)d_in[6];
    const float* k_b    = (const float*)d_in[7];
    const float* gv     = (const float*)d_in[8];
    const float* go     = (const float*)d_in[9];
    const float* v_base = (const float*)d_in[10];
    const float* v_a    = (const float*)d_in[11];
    const float* v_b    = (const float*)d_in[12];
    const float* o_base = (const float*)d_in[13];
    const float* o_a    = (const float*)d_in[14];
    const float* o_b    = (const float*)d_in[15];
    float* out = (float*)d_out;

    void *p_q, *p_k, *p_v, *p_ctx, *p_xa_q, *p_xa_k, *p_xa_v, *p_xa_o;
    void *p_list_v, *p_list_o, *p_cnt_v, *p_cnt_o, *p_ws_v, *p_ws_o;
    cudaGetSymbolAddress(&p_q, g_q);
    cudaGetSymbolAddress(&p_k, g_k);
    cudaGetSymbolAddress(&p_v, g_v);
    cudaGetSymbolAddress(&p_ctx, g_ctx);
    cudaGetSymbolAddress(&p_xa_q, g_xa_q);
    cudaGetSymbolAddress(&p_xa_k, g_xa_k);
    cudaGetSymbolAddress(&p_xa_v, g_xa_v);
    cudaGetSymbolAddress(&p_xa_o, g_xa_o);
    cudaGetSymbolAddress(&p_list_v, g_list_v);
    cudaGetSymbolAddress(&p_list_o, g_list_o);
    cudaGetSymbolAddress(&p_cnt_v, g_cnt_v);
    cudaGetSymbolAddress(&p_cnt_o, g_cnt_o);
    cudaGetSymbolAddress(&p_ws_v, g_wslot_v);
    cudaGetSymbolAddress(&p_ws_o, g_wslot_o);

    // reset per-replay state
    cudaMemsetAsync(p_v, 0, sizeof(float) * (size_t)T_ * H_);
    cudaMemsetAsync(out, 0, sizeof(float) * (size_t)T_ * H_);
    init_counts_kernel<<<1, 32>>>();

    // routing + LoRA down-projections
    routing_kernel<<<T_, 128>>>(x, gv, go);
    xa_qk_kernel<<<T_, 256>>>(x, q_a, k_a);
    xa_moe_kernel<<<dim3(T_, E_), 256>>>(x, v_a, (float*)p_xa_v);

    // Q / K projections (base + LoRA epilogue)
    gemm_proj_kernel<<<dim3(H_ / 128, T_ / 128), 256>>>(x, wq, (const float*)p_xa_q, q_b, (float*)p_q);
    gemm_proj_kernel<<<dim3(H_ / 128, T_ / 128), 256>>>(x, wk, (const float*)p_xa_k, k_b, (float*)p_k);

    // V MoE (gathered, top-2 only)
    gemm_moe_kernel<<<dim3(H_ / 128, T_ / 128, E_), 256>>>(
        x, v_base, v_b, (const float*)p_xa_v,
        (const int*)p_list_v, (const int*)p_cnt_v, (const float*)p_ws_v, (float*)p_v);

    // attention
    gemm_scores_kernel<<<dim3(S_ / 128, S_ / 128, B_ * NH_), 256>>>();
    softmax_kernel<<<(unsigned)((size_t)B_ * NH_ * S_), 256>>>(amask);
    gemm_ctx_kernel<<<dim3(1, S_ / 128, B_ * NH_), 256>>>();

    // O MoE on ctx (router computed from x), writes final output
    xa_moe_kernel<<<dim3(T_, E_), 256>>>((const float*)p_ctx, o_a, (float*)p_xa_o);
    gemm_moe_kernel<<<dim3(H_ / 128, T_ / 128, E_), 256>>>(
        (const float*)p_ctx, o_base, o_b, (const float*)p_xa_o,
        (const int*)p_list_o, (const int*)p_cnt_o, (const float*)p_ws_o, out);
}

// round 3
// speedup vs baseline: 2.3436x; 2.3436x over previous
#include <cuda_runtime.h>
#include <cuda_bf16.h>
#include <math.h>

typedef unsigned int u32;

// ---------------- problem constants ----------------
#define B_   2
#define S_   2048
#define H_   2048
#define NH_  16
#define DH_  128
#define E_   6
#define R_   16
#define T_   (B_ * S_)            // 4096 tokens
#define SCALING_ 8.0f
#define INV_SQRT_DH 0.08838834764831845f

// smem tile geometry: 128x32 fp32 tile stored as bf16 hi/lo, row stride 20 words (40 bf16)
#define SWW 20
#define TW  (128 * SWW)           // words per matrix tile = 2560
#define SMEM_SZ (2 * 4 * TW * 4)  // 2 stages x (Ahi,Alo,Bhi,Blo) x TW words x 4B = 81920

// ---------------- scratch (device globals) ----------------
__device__ float g_q[T_ * H_];
__device__ float g_k[T_ * H_];
__device__ float g_vt[T_ * H_];     // V transposed: [(b*H + n)] * S + s
__device__ float g_ctx[T_ * H_];
__device__ float g_scores[(size_t)B_ * NH_ * S_ * S_];
__device__ float g_xacat[T_ * 128];  // cols: 0-15 q, 16-31 k, 32+e*16 v-expert e
__device__ float g_xao[T_ * 128];    // cols: e*16 o-expert e (96 used)
__device__ float g_wcat[128 * H_];   // rows: q_a(16), k_a(16), v_a(96)
__device__ float g_wcat2[128 * H_];  // rows: o_a(96), rest stays zero
__device__ int   g_list_v[E_ * T_];
__device__ int   g_list_o[E_ * T_];
__device__ int   g_cnt_v[E_];
__device__ int   g_cnt_o[E_];
__device__ float g_wslot_v[T_ * 2];
__device__ float g_wslot_o[T_ * 2];

// ---------------- small helpers ----------------
__device__ __forceinline__ u32 pack_bf2(float a, float b) {
    __nv_bfloat162 t = __floats2bfloat162_rn(a, b);
    return *reinterpret_cast<u32*>(&t);
}

__device__ __forceinline__ void split4(float4 v, u32& h0, u32& h1, u32& l0, u32& l1) {
    __nv_bfloat162 p0 = __floats2bfloat162_rn(v.x, v.y);
    __nv_bfloat162 p1 = __floats2bfloat162_rn(v.z, v.w);
    h0 = *reinterpret_cast<u32*>(&p0);
    h1 = *reinterpret_cast<u32*>(&p1);
    l0 = pack_bf2(v.x - __low2float(p0), v.y - __high2float(p0));
    l1 = pack_bf2(v.z - __low2float(p1), v.w - __high2float(p1));
}

__device__ __forceinline__ void mma_bf16(float* c, u32 a0, u32 a1, u32 a2, u32 a3, u32 b0, u32 b1) {
    asm volatile(
        "mma.sync.aligned.m16n8k16.row.col.f32.bf16.bf16.f32 "
        "{%0,%1,%2,%3}, {%4,%5,%6,%7}, {%8,%9}, {%0,%1,%2,%3};"
        : "+f"(c[0]), "+f"(c[1]), "+f"(c[2]), "+f"(c[3])
        : "r"(a0), "r"(a1), "r"(a2), "r"(a3), "r"(b0), "r"(b1));
}

// load 128x32 fp32 tile into 16 staging regs (4 x float4 per thread)
__device__ __forceinline__ void ld_tile(const float* P, long ld, int kt,
                                        const int* tok, bool gather, int tid, float4* r) {
#pragma unroll
    for (int i = 0; i < 4; i++) {
        int f = tid + i * 256;
        int row = f >> 3, kc = (f & 7) * 4;
        size_t ro = gather ? (size_t)tok[row] * ld : (size_t)row * ld;
        r[i] = *(const float4*)(P + ro + kt + kc);
    }
}

// split + store staged tile into hi/lo bf16 smem
__device__ __forceinline__ void st_tile(u32* hi, u32* lo, int tid, const float4* r) {
#pragma unroll
    for (int i = 0; i < 4; i++) {
        int f = tid + i * 256;
        int row = f >> 3, kc = (f & 7) * 4;
        int w = row * SWW + (kc >> 1);
        u32 h0, h1, l0, l1;
        split4(r[i], h0, h1, l0, l1);
        hi[w] = h0; hi[w + 1] = h1; lo[w] = l0; lo[w + 1] = l1;
    }
}

// one k16 MMA step over a 128x128 block tile (3-term bf16 split)
__device__ __forceinline__ void compute_k16(const u32* __restrict__ Ahi, const u32* __restrict__ Alo,
                                            const u32* __restrict__ Bhi, const u32* __restrict__ Blo,
                                            int ks, int wm, int wn, int g, int tig,
                                            float (&acc)[4][4][4]) {
    int kw = ks * 8 + tig;
    u32 bh[4][2], bl[4][2];
#pragma unroll
    for (int nf = 0; nf < 4; nf++) {
        int n = wn * 32 + nf * 8 + g;
        bh[nf][0] = Bhi[n * SWW + kw]; bh[nf][1] = Bhi[n * SWW + kw + 4];
        bl[nf][0] = Blo[n * SWW + kw]; bl[nf][1] = Blo[n * SWW + kw + 4];
    }
#pragma unroll
    for (int mf = 0; mf < 4; mf++) {
        int m = wm * 64 + mf * 16 + g;
        u32 ah0 = Ahi[m * SWW + kw], ah1 = Ahi[(m + 8) * SWW + kw];
        u32 ah2 = Ahi[m * SWW + kw + 4], ah3 = Ahi[(m + 8) * SWW + kw + 4];
        u32 al0 = Alo[m * SWW + kw], al1 = Alo[(m + 8) * SWW + kw];
        u32 al2 = Alo[m * SWW + kw + 4], al3 = Alo[(m + 8) * SWW + kw + 4];
#pragma unroll
        for (int nf = 0; nf < 4; nf++) {
            mma_bf16(acc[mf][nf], ah0, ah1, ah2, ah3, bh[nf][0], bh[nf][1]);
            mma_bf16(acc[mf][nf], ah0, ah1, ah2, ah3, bl[nf][0], bl[nf][1]);
            mma_bf16(acc[mf][nf], al0, al1, al2, al3, bh[nf][0], bh[nf][1]);
        }
    }
}

// ---------------- the one NT GEMM kernel, 5 modes ----------------
enum { M_PROJ = 0, M_XA = 1, M_MOE = 2, M_MOEVT = 3, M_SCORES = 4, M_CTX = 5 };

template <int MODE>
__global__ void __launch_bounds__(256) tc_gemm(
    const float* __restrict__ Ab, const float* __restrict__ Bb, float* __restrict__ Cb,
    const float* __restrict__ Lab, const float* __restrict__ Lbb,
    const int* __restrict__ glist, const int* __restrict__ gcnt,
    const float* __restrict__ gw) {
    constexpr bool GATHER = (MODE == M_MOE || MODE == M_MOEVT);
    constexpr bool LORA = (MODE == M_PROJ || MODE == M_MOE || MODE == M_MOEVT);
    extern __shared__ u32 smw[];
    __shared__ int esm[128];
    __shared__ int tok[128];

    int tid = threadIdx.x;
    int m0 = blockIdx.y * 128, n0 = blockIdx.x * 128, z = blockIdx.z;

    const float *A, *Bp, *La = nullptr, *Lb = nullptr;
    float* C = nullptr;
    long lda, ldb, ldc = 0;
    int K;
    int ldla = 0;
    float scale = 1.0f;

    if constexpr (MODE == M_PROJ) {
        A = Ab + (size_t)m0 * H_;
        Bp = Bb + (size_t)n0 * H_;
        C = Cb + (size_t)m0 * H_ + n0;
        lda = ldb = H_; ldc = H_; K = H_;
        La = Lab + (size_t)m0 * 128; ldla = 128;
        Lb = Lbb + (size_t)n0 * R_;
    } else if constexpr (MODE == M_XA) {
        A = Ab + (size_t)m0 * H_;
        Bp = Bb;                              // 128 x H weight concat
        C = Cb + (size_t)m0 * 128;
        lda = ldb = H_; ldc = 128; K = H_;
    } else if constexpr (GATHER) {
        A = Ab;                               // absolute rows via tok
        Bp = Bb + (size_t)z * H_ * H_ + (size_t)n0 * H_;
        C = Cb;                               // handled in epilogue
        lda = ldb = H_; K = H_;
        La = Lab + z * R_; ldla = 128;        // Lab already offset (+32 cols for V)
        Lb = Lbb + (size_t)z * H_ * R_ + (size_t)n0 * R_;
    } else if constexpr (MODE == M_SCORES) {
        int b = z >> 4, h = z & 15;
        A = Ab + ((size_t)b * S_ + m0) * H_ + h * DH_;
        Bp = Bb + ((size_t)b * S_ + n0) * H_ + h * DH_;
        C = Cb + (size_t)z * S_ * S_ + (size_t)m0 * S_ + n0;
        lda = ldb = H_; ldc = S_; K = DH_;
        scale = INV_SQRT_DH;
    } else {  // M_CTX
        A = Ab + (size_t)z * S_ * S_ + (size_t)m0 * S_;
        Bp = Bb + (size_t)z * DH_ * S_;
        int b = z >> 4, h = z & 15;
        C = Cb + ((size_t)b * S_ + m0) * H_ + h * DH_;
        lda = S_; ldb = S_; ldc = H_; K = S_;
    }

    if constexpr (GATHER) {
        int count = gcnt[z];
        if (m0 >= count) return;
        if (tid < 128) {
            int idx = m0 + tid;
            int en = (idx < count) ? glist[z * T_ + idx] : -1;
            esm[tid] = en;
            tok[tid] = (en >= 0) ? (en >> 1) : 0;
        }
        __syncthreads();
    }

    int wid = tid >> 5, lane = tid & 31;
    int wm = wid & 1, wn = wid >> 1, g = lane >> 2, tig = lane & 3;

    float acc[4][4][4];
#pragma unroll
    for (int a = 0; a < 4; a++)
#pragma unroll
        for (int b = 0; b < 4; b++)
#pragma unroll
            for (int c = 0; c < 4; c++) acc[a][b][c] = 0.f;

    float4 ra[4], rb[4];
    ld_tile(A, lda, 0, tok, GATHER, tid, ra);
    ld_tile(Bp, ldb, 0, nullptr, false, tid, rb);
    st_tile(smw + 0 * TW, smw + 1 * TW, tid, ra);
    st_tile(smw + 2 * TW, smw + 3 * TW, tid, rb);
    __syncthreads();

    int nk = K / 32;
    for (int it = 0; it < nk; it++) {
        int cur = it & 1;
        if (it + 1 < nk) {
            ld_tile(A, lda, (it + 1) * 32, tok, GATHER, tid, ra);
            ld_tile(Bp, ldb, (it + 1) * 32, nullptr, false, tid, rb);
        }
        const u32* ah = smw + (cur * 4 + 0) * TW;
        const u32* al = smw + (cur * 4 + 1) * TW;
        const u32* bh = smw + (cur * 4 + 2) * TW;
        const u32* bl = smw + (cur * 4 + 3) * TW;
        compute_k16(ah, al, bh, bl, 0, wm, wn, g, tig, acc);
        compute_k16(ah, al, bh, bl, 1, wm, wn, g, tig, acc);
        if (it + 1 < nk) {
            int nx = cur ^ 1;
            st_tile(smw + (nx * 4 + 0) * TW, smw + (nx * 4 + 1) * TW, tid, ra);
            st_tile(smw + (nx * 4 + 2) * TW, smw + (nx * 4 + 3) * TW, tid, rb);
        }
        __syncthreads();
    }

    if constexpr (LORA) {
        // one extra k16 step: A = SCALING * La (gathered rows for MOE), B = Lb
#pragma unroll
        for (int i = 0; i < 2; i++) {
            int f = tid + i * 256;
            int row = f >> 2, kc = (f & 3) * 4;
            size_t ro = GATHER ? (size_t)tok[row] * ldla : (size_t)row * ldla;
            float4 v = *(const float4*)(La + ro + kc);
            v.x *= SCALING_; v.y *= SCALING_; v.z *= SCALING_; v.w *= SCALING_;
            u32 h0, h1, l0, l1;
            split4(v, h0, h1, l0, l1);
            int w = row * SWW + (kc >> 1);
            smw[0 * TW + w] = h0; smw[0 * TW + w + 1] = h1;
            smw[1 * TW + w] = l0; smw[1 * TW + w + 1] = l1;
            float4 u = *(const float4*)(Lb + (size_t)row * R_ + kc);
            split4(u, h0, h1, l0, l1);
            smw[2 * TW + w] = h0; smw[2 * TW + w + 1] = h1;
            smw[3 * TW + w] = l0; smw[3 * TW + w + 1] = l1;
        }
        __syncthreads();
        compute_k16(smw, smw + TW, smw + 2 * TW, smw + 3 * TW, 0, wm, wn, g, tig, acc);
    }

    // epilogue
    if constexpr (GATHER) {
#pragma unroll
        for (int mf = 0; mf < 4; mf++) {
#pragma unroll
            for (int half = 0; half < 2; half++) {
                int lr = wm * 64 + mf * 16 + g + half * 8;
                int en = esm[lr];
                if (en < 0) continue;
                float w = gw[en];
                int t = en >> 1;
#pragma unroll
                for (int nf = 0; nf < 4; nf++) {
                    int n = n0 + wn * 32 + nf * 8 + tig * 2;
                    float c0 = acc[mf][nf][half * 2 + 0] * w;
                    float c1 = acc[mf][nf][half * 2 + 1] * w;
                    if constexpr (MODE == M_MOE) {
                        float* p = Cb + (size_t)t * H_ + n;
                        atomicAdd(p, c0);
                        atomicAdd(p + 1, c1);
                    } else {
                        int b = t >> 11, s = t & (S_ - 1);
                        atomicAdd(Cb + ((size_t)(b * H_ + n)) * S_ + s, c0);
                        atomicAdd(Cb + ((size_t)(b * H_ + n + 1)) * S_ + s, c1);
                    }
                }
            }
        }
    } else {
#pragma unroll
        for (int mf = 0; mf < 4; mf++) {
#pragma unroll
            for (int half = 0; half < 2; half++) {
                int m = wm * 64 + mf * 16 + g + half * 8;
#pragma unroll
                for (int nf = 0; nf < 4; nf++) {
                    int n = wn * 32 + nf * 8 + tig * 2;
                    float2 v = {scale * acc[mf][nf][half * 2 + 0],
                                scale * acc[mf][nf][half * 2 + 1]};
                    *(float2*)(C + (size_t)m * ldc + n) = v;
                }
            }
        }
    }
}

// ---------------- init counts ----------------
__global__ void init_counts_kernel() {
    if (threadIdx.x < E_) {
        g_cnt_v[threadIdx.x] = 0;
        g_cnt_o[threadIdx.x] = 0;
    }
}

// ---------------- routing ----------------
__global__ void routing_kernel(const float* __restrict__ x,
                               const float* __restrict__ gv,
                               const float* __restrict__ go) {
    int t = blockIdx.x;
    const float* xt = x + (size_t)t * H_;
    float pv[E_], po[E_];
#pragma unroll
    for (int e = 0; e < E_; e++) { pv[e] = 0.f; po[e] = 0.f; }
    for (int k = threadIdx.x; k < H_; k += 128) {
        float xv = xt[k];
#pragma unroll
        for (int e = 0; e < E_; e++) {
            pv[e] += xv * gv[e * H_ + k];
            po[e] += xv * go[e * H_ + k];
        }
    }
    __shared__ float red[2 * E_][128];
#pragma unroll
    for (int e = 0; e < E_; e++) {
        red[e][threadIdx.x] = pv[e];
        red[E_ + e][threadIdx.x] = po[e];
    }
    __syncthreads();
    if (threadIdx.x < 2 * E_) {
        float s = 0.f;
        for (int i = 0; i < 128; i++) s += red[threadIdx.x][i];
        red[threadIdx.x][0] = s;
    }
    __syncthreads();
    if (threadIdx.x < 2) {
        bool isO = (threadIdx.x == 1);
        float sc[E_];
#pragma unroll
        for (int e = 0; e < E_; e++) {
            float d = red[(isO ? E_ : 0) + e][0];
            sc[e] = 1.f / (1.f + expf(-d));
        }
        int e0 = 0;
        for (int e = 1; e < E_; e++) if (sc[e] > sc[e0]) e0 = e;
        int e1 = -1;
        for (int e = 0; e < E_; e++) {
            if (e == e0) continue;
            if (e1 < 0 || sc[e] > sc[e1]) e1 = e;
        }
        float t1 = expf(sc[e1] - sc[e0]);
        float w0 = 1.f / (1.f + t1);
        float w1 = t1 / (1.f + t1);
        if (!isO) {
            g_wslot_v[t * 2 + 0] = w0;
            g_wslot_v[t * 2 + 1] = w1;
            int p0 = atomicAdd(&g_cnt_v[e0], 1); g_list_v[e0 * T_ + p0] = t * 2 + 0;
            int p1 = atomicAdd(&g_cnt_v[e1], 1); g_list_v[e1 * T_ + p1] = t * 2 + 1;
        } else {
            g_wslot_o[t * 2 + 0] = w0;
            g_wslot_o[t * 2 + 1] = w1;
            int p0 = atomicAdd(&g_cnt_o[e0], 1); g_list_o[e0 * T_ + p0] = t * 2 + 0;
            int p1 = atomicAdd(&g_cnt_o[e1], 1); g_list_o[e1 * T_ + p1] = t * 2 + 1;
        }
    }
}

// ---------------- register-resident softmax ----------------
__global__ void softmax_kernel(const float* __restrict__ amask) {
    size_t row = blockIdx.x;
    int b = (int)(row / ((size_t)NH_ * S_));
    float* p = g_scores + row * S_;
    const float* mk = amask + (size_t)b * S_;
    int tid = threadIdx.x;
    int lane = tid & 31, wrp = tid >> 5;
    __shared__ float red[8];

    float v[8];
#pragma unroll
    for (int i = 0; i < 8; i++) {
        int k = tid + i * 256;
        v[i] = p[k] + (1.f - mk[k]) * (-10000.f);
    }
    float mx = v[0];
#pragma unroll
    for (int i = 1; i < 8; i++) mx = fmaxf(mx, v[i]);
#pragma unroll
    for (int o = 16; o > 0; o >>= 1) mx = fmaxf(mx, __shfl_xor_sync(0xffffffffu, mx, o));
    if (lane == 0) red[wrp] = mx;
    __syncthreads();
    float MX = red[0];
#pragma unroll
    for (int w = 1; w < 8; w++) MX = fmaxf(MX, red[w]);
    __syncthreads();

    float sum = 0.f;
#pragma unroll
    for (int i = 0; i < 8; i++) {
        v[i] = __expf(v[i] - MX);
        sum += v[i];
    }
#pragma unroll
    for (int o = 16; o > 0; o >>= 1) sum += __shfl_xor_sync(0xffffffffu, sum, o);
    if (lane == 0) red[wrp] = sum;
    __syncthreads();
    float SM = red[0];
#pragma unroll
    for (int w = 1; w < 8; w++) SM += red[w];
    float inv = 1.f / SM;
#pragma unroll
    for (int i = 0; i < 8; i++) p[tid + i * 256] = v[i] * inv;
}

// ---------------- launcher ----------------
extern "C" void kernel_launch(void* const* d_in, const int* in_sizes, int n_in,
                              void* d_out, int out_size) {
    const float* x      = (const float*)d_in[0];
    const float* amask  = (const float*)d_in[1];
    const float* wq     = (const float*)d_in[2];
    const float* wk     = (const float*)d_in[3];
    const float* q_a    = (const float*)d_in[4];
    const float* q_b    = (const float*)d_in[5];
    const float* k_a    = (const float*)d_in[6];
    const float* k_b    = (const float*)d_in[7];
    const float* gv     = (const float*)d_in[8];
    const float* go     = (const float*)d_in[9];
    const float* v_base = (const float*)d_in[10];
    const float* v_a    = (const float*)d_in[11];
    const float* v_b    = (const float*)d_in[12];
    const float* o_base = (const float*)d_in[13];
    const float* o_a    = (const float*)d_in[14];
    const float* o_b    = (const float*)d_in[15];
    float* out = (float*)d_out;

    void *p_q, *p_k, *p_vt, *p_ctx, *p_scores, *p_xacat, *p_xao, *p_wcat, *p_wcat2;
    void *p_list_v, *p_list_o, *p_cnt_v, *p_cnt_o, *p_ws_v, *p_ws_o;
    cudaGetSymbolAddress(&p_q, g_q);
    cudaGetSymbolAddress(&p_k, g_k);
    cudaGetSymbolAddress(&p_vt, g_vt);
    cudaGetSymbolAddress(&p_ctx, g_ctx);
    cudaGetSymbolAddress(&p_scores, g_scores);
    cudaGetSymbolAddress(&p_xacat, g_xacat);
    cudaGetSymbolAddress(&p_xao, g_xao);
    cudaGetSymbolAddress(&p_wcat, g_wcat);
    cudaGetSymbolAddress(&p_wcat2, g_wcat2);
    cudaGetSymbolAddress(&p_list_v, g_list_v);
    cudaGetSymbolAddress(&p_list_o, g_list_o);
    cudaGetSymbolAddress(&p_cnt_v, g_cnt_v);
    cudaGetSymbolAddress(&p_cnt_o, g_cnt_o);
    cudaGetSymbolAddress(&p_ws_v, g_wslot_v);
    cudaGetSymbolAddress(&p_ws_o, g_wslot_o);

    cudaFuncSetAttribute(tc_gemm<M_PROJ>,   cudaFuncAttributeMaxDynamicSharedMemorySize, SMEM_SZ);
    cudaFuncSetAttribute(tc_gemm<M_XA>,     cudaFuncAttributeMaxDynamicSharedMemorySize, SMEM_SZ);
    cudaFuncSetAttribute(tc_gemm<M_MOE>,    cudaFuncAttributeMaxDynamicSharedMemorySize, SMEM_SZ);
    cudaFuncSetAttribute(tc_gemm<M_MOEVT>,  cudaFuncAttributeMaxDynamicSharedMemorySize, SMEM_SZ);
    cudaFuncSetAttribute(tc_gemm<M_SCORES>, cudaFuncAttributeMaxDynamicSharedMemorySize, SMEM_SZ);
    cudaFuncSetAttribute(tc_gemm<M_CTX>,    cudaFuncAttributeMaxDynamicSharedMemorySize, SMEM_SZ);

    // assemble LoRA-A weight concats (contiguous D2D copies)
    cudaMemcpyAsync((float*)p_wcat,             q_a, sizeof(float) * R_ * H_,      cudaMemcpyDeviceToDevice);
    cudaMemcpyAsync((float*)p_wcat + 16 * H_,   k_a, sizeof(float) * R_ * H_,      cudaMemcpyDeviceToDevice);
    cudaMemcpyAsync((float*)p_wcat + 32 * H_,   v_a, sizeof(float) * E_ * R_ * H_, cudaMemcpyDeviceToDevice);
    cudaMemcpyAsync((float*)p_wcat2,            o_a, sizeof(float) * E_ * R_ * H_, cudaMemcpyDeviceToDevice);

    // reset per-replay state
    cudaMemsetAsync(p_vt, 0, sizeof(float) * (size_t)T_ * H_);
    cudaMemsetAsync(out, 0, sizeof(float) * (size_t)T_ * H_);
    init_counts_kernel<<<1, 32>>>();
    routing_kernel<<<T_, 128>>>(x, gv, go);

    // all LoRA-A down-projections in one tensor-core GEMM: xacat[T,128] = x @ wcat^T
    tc_gemm<M_XA><<<dim3(1, T_ / 128), 256, SMEM_SZ>>>(
        x, (const float*)p_wcat, (float*)p_xacat, nullptr, nullptr, nullptr, nullptr, nullptr);

    // Q / K projections (base + LoRA epilogue)
    tc_gemm<M_PROJ><<<dim3(H_ / 128, T_ / 128), 256, SMEM_SZ>>>(
        x, wq, (float*)p_q, (const float*)p_xacat + 0, q_b, nullptr, nullptr, nullptr);
    tc_gemm<M_PROJ><<<dim3(H_ / 128, T_ / 128), 256, SMEM_SZ>>>(
        x, wk, (float*)p_k, (const float*)p_xacat + 16, k_b, nullptr, nullptr, nullptr);

    // V MoE (gathered, top-2), writes TRANSPOSED g_vt
    tc_gemm<M_MOEVT><<<dim3(H_ / 128, T_ / 128, E_), 256, SMEM_SZ>>>(
        x, v_base, (float*)p_vt, (const float*)p_xacat + 32, v_b,
        (const int*)p_list_v, (const int*)p_cnt_v, (const float*)p_ws_v);

    // attention
    tc_gemm<M_SCORES><<<dim3(S_ / 128, S_ / 128, B_ * NH_), 256, SMEM_SZ>>>(
        (const float*)p_q, (const float*)p_k, (float*)p_scores,
        nullptr, nullptr, nullptr, nullptr, nullptr);
    softmax_kernel<<<(unsigned)((size_t)B_ * NH_ * S_), 256>>>(amask);
    tc_gemm<M_CTX><<<dim3(1, S_ / 128, B_ * NH_), 256, SMEM_SZ>>>(
        (const float*)p_scores, (const float*)p_vt, (float*)p_ctx,
        nullptr, nullptr, nullptr, nullptr, nullptr);

    // O-path LoRA down-projections + O MoE into final output
    tc_gemm<M_XA><<<dim3(1, T_ / 128), 256, SMEM_SZ>>>(
        (const float*)p_ctx, (const float*)p_wcat2, (float*)p_xao,
        nullptr, nullptr, nullptr, nullptr, nullptr);
    tc_gemm<M_MOE><<<dim3(H_ / 128, T_ / 128, E_), 256, SMEM_SZ>>>(
        (const float*)p_ctx, o_base, out, (const float*)p_xao, o_b,
        (const int*)p_list_o, (const int*)p_cnt_o, (const float*)p_ws_o);
}

// round 4
// speedup vs baseline: 2.3660x; 1.0095x over previous
#include <cuda_runtime.h>
#include <cuda_bf16.h>
#include <math.h>

typedef unsigned int u32;

// ---------------- problem constants ----------------
#define B_   2
#define S_   2048
#define H_   2048
#define NH_  16
#define DH_  128
#define E_   6
#define R_   16
#define T_   (B_ * S_)            // 4096 tokens
#define SCALING_ 8.0f
#define INV_SQRT_DH 0.08838834764831845f

// smem tile geometry: 128x32 fp32 tile stored as bf16 hi/lo, row stride 20 words (40 bf16)
#define SWW 20
#define TW  (128 * SWW)           // words per matrix tile = 2560
#define SMEM_SZ (2 * 4 * TW * 4)  // 2 stages x (Ahi,Alo,Bhi,Blo) x TW words x 4B = 81920

// ---------------- scratch (device globals) ----------------
__device__ float g_q[T_ * H_];
__device__ float g_k[T_ * H_];
__device__ float g_vt[T_ * H_];     // V transposed: [(b*H + n)] * S + s
__device__ float g_ctx[T_ * H_];
__device__ float g_scores[(size_t)B_ * NH_ * S_ * S_];
__device__ float g_xacat[T_ * 128];  // cols: 0-15 q, 16-31 k, 32+e*16 v-expert e
__device__ float g_xao[T_ * 128];    // cols: e*16 o-expert e (96 used)
__device__ float g_wcat[128 * H_];   // rows: q_a(16), k_a(16), v_a(96)
__device__ float g_wcat2[128 * H_];  // rows: o_a(96), rest stays zero
__device__ int   g_list_v[E_ * T_];
__device__ int   g_list_o[E_ * T_];
__device__ int   g_cnt_v[E_];
__device__ int   g_cnt_o[E_];
__device__ float g_wslot_v[T_ * 2];
__device__ float g_wslot_o[T_ * 2];

// ---------------- small helpers ----------------
__device__ __forceinline__ u32 pack_bf2(float a, float b) {
    __nv_bfloat162 t = __floats2bfloat162_rn(a, b);
    return *reinterpret_cast<u32*>(&t);
}

__device__ __forceinline__ void split4(float4 v, u32& h0, u32& h1, u32& l0, u32& l1) {
    __nv_bfloat162 p0 = __floats2bfloat162_rn(v.x, v.y);
    __nv_bfloat162 p1 = __floats2bfloat162_rn(v.z, v.w);
    h0 = *reinterpret_cast<u32*>(&p0);
    h1 = *reinterpret_cast<u32*>(&p1);
    l0 = pack_bf2(v.x - __low2float(p0), v.y - __high2float(p0));
    l1 = pack_bf2(v.z - __low2float(p1), v.w - __high2float(p1));
}

__device__ __forceinline__ void mma_bf16(float* c, u32 a0, u32 a1, u32 a2, u32 a3, u32 b0, u32 b1) {
    asm volatile(
        "mma.sync.aligned.m16n8k16.row.col.f32.bf16.bf16.f32 "
        "{%0,%1,%2,%3}, {%4,%5,%6,%7}, {%8,%9}, {%0,%1,%2,%3};"
        : "+f"(c[0]), "+f"(c[1]), "+f"(c[2]), "+f"(c[3])
        : "r"(a0), "r"(a1), "r"(a2), "r"(a3), "r"(b0), "r"(b1));
}

// load ONE 128x32 fp32 tile into 4 float4 staging regs
__device__ __forceinline__ void ld_mat(const float* P, long ld, int kt,
                                       const int* tok, bool gather, int tid, float4* r) {
#pragma unroll
    for (int i = 0; i < 4; i++) {
        int f = tid + i * 256;
        int row = f >> 3, kc = (f & 7) * 4;
        size_t ro = gather ? (size_t)tok[row] * ld : (size_t)row * ld;
        r[i] = *(const float4*)(P + ro + kt + kc);
    }
}

// split + store ONE staged tile into hi/lo bf16 smem
__device__ __forceinline__ void st_mat(u32* hi, u32* lo, int tid, const float4* r) {
#pragma unroll
    for (int i = 0; i < 4; i++) {
        int f = tid + i * 256;
        int row = f >> 3, kc = (f & 7) * 4;
        int w = row * SWW + (kc >> 1);
        u32 h0, h1, l0, l1;
        split4(r[i], h0, h1, l0, l1);
        hi[w] = h0; hi[w + 1] = h1; lo[w] = l0; lo[w + 1] = l1;
    }
}

// one k16 MMA step over a 128x128 block tile (3-term bf16 split)
__device__ __forceinline__ void compute_k16(const u32* __restrict__ Ahi, const u32* __restrict__ Alo,
                                            const u32* __restrict__ Bhi, const u32* __restrict__ Blo,
                                            int ks, int wm, int wn, int g, int tig,
                                            float (&acc)[4][4][4]) {
    int kw = ks * 8 + tig;
    u32 bh[4][2], bl[4][2];
#pragma unroll
    for (int nf = 0; nf < 4; nf++) {
        int n = wn * 32 + nf * 8 + g;
        bh[nf][0] = Bhi[n * SWW + kw]; bh[nf][1] = Bhi[n * SWW + kw + 4];
        bl[nf][0] = Blo[n * SWW + kw]; bl[nf][1] = Blo[n * SWW + kw + 4];
    }
#pragma unroll
    for (int mf = 0; mf < 4; mf++) {
        int m = wm * 64 + mf * 16 + g;
        u32 ah0 = Ahi[m * SWW + kw], ah1 = Ahi[(m + 8) * SWW + kw];
        u32 ah2 = Ahi[m * SWW + kw + 4], ah3 = Ahi[(m + 8) * SWW + kw + 4];
        u32 al0 = Alo[m * SWW + kw], al1 = Alo[(m + 8) * SWW + kw];
        u32 al2 = Alo[m * SWW + kw + 4], al3 = Alo[(m + 8) * SWW + kw + 4];
#pragma unroll
        for (int nf = 0; nf < 4; nf++) {
            mma_bf16(acc[mf][nf], ah0, ah1, ah2, ah3, bh[nf][0], bh[nf][1]);
            mma_bf16(acc[mf][nf], ah0, ah1, ah2, ah3, bl[nf][0], bl[nf][1]);
            mma_bf16(acc[mf][nf], al0, al1, al2, al3, bh[nf][0], bh[nf][1]);
        }
    }
}

// ---------------- the one NT GEMM kernel, 6 modes ----------------
enum { M_PROJ = 0, M_XA = 1, M_MOE = 2, M_MOEVT = 3, M_SCORES = 4, M_CTX = 5 };

template <int MODE>
__global__ void __launch_bounds__(256, 2) tc_gemm(
    const float* __restrict__ Ab, const float* __restrict__ Bb, float* __restrict__ Cb,
    const float* __restrict__ Lab, const float* __restrict__ Lbb,
    const int* __restrict__ glist, const int* __restrict__ gcnt,
    const float* __restrict__ gw) {
    constexpr bool GATHER = (MODE == M_MOE || MODE == M_MOEVT);
    constexpr bool LORA = (MODE == M_PROJ || MODE == M_MOE || MODE == M_MOEVT);
    extern __shared__ u32 smw[];
    __shared__ int esm[128];
    __shared__ int tok[128];

    int tid = threadIdx.x;
    int m0 = blockIdx.y * 128, n0 = blockIdx.x * 128, z = blockIdx.z;

    const float *A, *Bp, *La = nullptr, *Lb = nullptr;
    float* C = nullptr;
    long lda, ldb, ldc = 0;
    int K;
    int ldla = 0;
    float scale = 1.0f;

    if constexpr (MODE == M_PROJ) {
        A = Ab + (size_t)m0 * H_;
        Bp = Bb + (size_t)n0 * H_;
        C = Cb + (size_t)m0 * H_ + n0;
        lda = ldb = H_; ldc = H_; K = H_;
        La = Lab + (size_t)m0 * 128; ldla = 128;
        Lb = Lbb + (size_t)n0 * R_;
    } else if constexpr (MODE == M_XA) {
        A = Ab + (size_t)m0 * H_;
        Bp = Bb;                              // 128 x H weight concat
        C = Cb + (size_t)m0 * 128;
        lda = ldb = H_; ldc = 128; K = H_;
    } else if constexpr (GATHER) {
        A = Ab;                               // absolute rows via tok
        Bp = Bb + (size_t)z * H_ * H_ + (size_t)n0 * H_;
        C = Cb;                               // handled in epilogue
        lda = ldb = H_; K = H_;
        La = Lab + z * R_; ldla = 128;        // Lab already offset (+32 cols for V)
        Lb = Lbb + (size_t)z * H_ * R_ + (size_t)n0 * R_;
    } else if constexpr (MODE == M_SCORES) {
        int b = z >> 4, h = z & 15;
        A = Ab + ((size_t)b * S_ + m0) * H_ + h * DH_;
        Bp = Bb + ((size_t)b * S_ + n0) * H_ + h * DH_;
        C = Cb + (size_t)z * S_ * S_ + (size_t)m0 * S_ + n0;
        lda = ldb = H_; ldc = S_; K = DH_;
        scale = INV_SQRT_DH;
    } else {  // M_CTX
        A = Ab + (size_t)z * S_ * S_ + (size_t)m0 * S_;
        Bp = Bb + (size_t)z * DH_ * S_;
        int b = z >> 4, h = z & 15;
        C = Cb + ((size_t)b * S_ + m0) * H_ + h * DH_;
        lda = S_; ldb = S_; ldc = H_; K = S_;
    }

    if constexpr (GATHER) {
        int count = gcnt[z];
        if (m0 >= count) return;
        if (tid < 128) {
            int idx = m0 + tid;
            int en = (idx < count) ? glist[z * T_ + idx] : -1;
            esm[tid] = en;
            tok[tid] = (en >= 0) ? (en >> 1) : 0;
        }
        __syncthreads();
    }

    int wid = tid >> 5, lane = tid & 31;
    int wm = wid & 1, wn = wid >> 1, g = lane >> 2, tig = lane & 3;

    float acc[4][4][4];
#pragma unroll
    for (int a = 0; a < 4; a++)
#pragma unroll
        for (int b = 0; b < 4; b++)
#pragma unroll
            for (int c = 0; c < 4; c++) acc[a][b][c] = 0.f;

    float4 r[4];
    // prologue: fill stage 0 (A then B through the single staging buffer)
    ld_mat(A, lda, 0, tok, GATHER, tid, r);
    st_mat(smw + 0 * TW, smw + 1 * TW, tid, r);
    ld_mat(Bp, ldb, 0, nullptr, false, tid, r);
    st_mat(smw + 2 * TW, smw + 3 * TW, tid, r);
    __syncthreads();

    int nk = K / 32;
    for (int it = 0; it < nk; it++) {
        int cur = it & 1, nx = cur ^ 1;
        const u32* ah = smw + (cur * 4 + 0) * TW;
        const u32* al = smw + (cur * 4 + 1) * TW;
        const u32* bh = smw + (cur * 4 + 2) * TW;
        const u32* bl = smw + (cur * 4 + 3) * TW;
        bool pf = (it + 1 < nk);
        // stage A(next) around first k16, stage B(next) around second k16
        if (pf) ld_mat(A, lda, (it + 1) * 32, tok, GATHER, tid, r);
        compute_k16(ah, al, bh, bl, 0, wm, wn, g, tig, acc);
        if (pf) st_mat(smw + (nx * 4 + 0) * TW, smw + (nx * 4 + 1) * TW, tid, r);
        if (pf) ld_mat(Bp, ldb, (it + 1) * 32, nullptr, false, tid, r);
        compute_k16(ah, al, bh, bl, 1, wm, wn, g, tig, acc);
        if (pf) st_mat(smw + (nx * 4 + 2) * TW, smw + (nx * 4 + 3) * TW, tid, r);
        __syncthreads();
    }

    if constexpr (LORA) {
        // one extra k16 step: A = SCALING * La (gathered rows for MOE), B = Lb
#pragma unroll
        for (int i = 0; i < 2; i++) {
            int f = tid + i * 256;
            int row = f >> 2, kc = (f & 3) * 4;
            size_t ro = GATHER ? (size_t)tok[row] * ldla : (size_t)row * ldla;
            float4 v = *(const float4*)(La + ro + kc);
            v.x *= SCALING_; v.y *= SCALING_; v.z *= SCALING_; v.w *= SCALING_;
            u32 h0, h1, l0, l1;
            split4(v, h0, h1, l0, l1);
            int w = row * SWW + (kc >> 1);
            smw[0 * TW + w] = h0; smw[0 * TW + w + 1] = h1;
            smw[1 * TW + w] = l0; smw[1 * TW + w + 1] = l1;
            float4 u = *(const float4*)(Lb + (size_t)row * R_ + kc);
            split4(u, h0, h1, l0, l1);
            smw[2 * TW + w] = h0; smw[2 * TW + w + 1] = h1;
            smw[3 * TW + w] = l0; smw[3 * TW + w + 1] = l1;
        }
        __syncthreads();
        compute_k16(smw, smw + TW, smw + 2 * TW, smw + 3 * TW, 0, wm, wn, g, tig, acc);
    }

    // epilogue
    if constexpr (GATHER) {
#pragma unroll
        for (int mf = 0; mf < 4; mf++) {
#pragma unroll
            for (int half = 0; half < 2; half++) {
                int lr = wm * 64 + mf * 16 + g + half * 8;
                int en = esm[lr];
                if (en < 0) continue;
                float w = gw[en];
                int t = en >> 1;
#pragma unroll
                for (int nf = 0; nf < 4; nf++) {
                    int n = n0 + wn * 32 + nf * 8 + tig * 2;
                    float c0 = acc[mf][nf][half * 2 + 0] * w;
                    float c1 = acc[mf][nf][half * 2 + 1] * w;
                    if constexpr (MODE == M_MOE) {
                        float* p = Cb + (size_t)t * H_ + n;
                        atomicAdd(p, c0);
                        atomicAdd(p + 1, c1);
                    } else {
                        int b = t >> 11, s = t & (S_ - 1);
                        atomicAdd(Cb + ((size_t)(b * H_ + n)) * S_ + s, c0);
                        atomicAdd(Cb + ((size_t)(b * H_ + n + 1)) * S_ + s, c1);
                    }
                }
            }
        }
    } else {
#pragma unroll
        for (int mf = 0; mf < 4; mf++) {
#pragma unroll
            for (int half = 0; half < 2; half++) {
                int m = wm * 64 + mf * 16 + g + half * 8;
#pragma unroll
                for (int nf = 0; nf < 4; nf++) {
                    int n = wn * 32 + nf * 8 + tig * 2;
                    float2 v = {scale * acc[mf][nf][half * 2 + 0],
                                scale * acc[mf][nf][half * 2 + 1]};
                    *(float2*)(C + (size_t)m * ldc + n) = v;
                }
            }
        }
    }
}

// ---------------- init counts ----------------
__global__ void init_counts_kernel() {
    if (threadIdx.x < E_) {
        g_cnt_v[threadIdx.x] = 0;
        g_cnt_o[threadIdx.x] = 0;
    }
}

// ---------------- routing ----------------
__global__ void routing_kernel(const float* __restrict__ x,
                               const float* __restrict__ gv,
                               const float* __restrict__ go) {
    int t = blockIdx.x;
    const float* xt = x + (size_t)t * H_;
    float pv[E_], po[E_];
#pragma unroll
    for (int e = 0; e < E_; e++) { pv[e] = 0.f; po[e] = 0.f; }
    for (int k = threadIdx.x; k < H_; k += 128) {
        float xv = xt[k];
#pragma unroll
        for (int e = 0; e < E_; e++) {
            pv[e] += xv * gv[e * H_ + k];
            po[e] += xv * go[e * H_ + k];
        }
    }
    __shared__ float red[2 * E_][128];
#pragma unroll
    for (int e = 0; e < E_; e++) {
        red[e][threadIdx.x] = pv[e];
        red[E_ + e][threadIdx.x] = po[e];
    }
    __syncthreads();
    if (threadIdx.x < 2 * E_) {
        float s = 0.f;
        for (int i = 0; i < 128; i++) s += red[threadIdx.x][i];
        red[threadIdx.x][0] = s;
    }
    __syncthreads();
    if (threadIdx.x < 2) {
        bool isO = (threadIdx.x == 1);
        float sc[E_];
#pragma unroll
        for (int e = 0; e < E_; e++) {
            float d = red[(isO ? E_ : 0) + e][0];
            sc[e] = 1.f / (1.f + expf(-d));
        }
        int e0 = 0;
        for (int e = 1; e < E_; e++) if (sc[e] > sc[e0]) e0 = e;
        int e1 = -1;
        for (int e = 0; e < E_; e++) {
            if (e == e0) continue;
            if (e1 < 0 || sc[e] > sc[e1]) e1 = e;
        }
        float t1 = expf(sc[e1] - sc[e0]);
        float w0 = 1.f / (1.f + t1);
        float w1 = t1 / (1.f + t1);
        if (!isO) {
            g_wslot_v[t * 2 + 0] = w0;
            g_wslot_v[t * 2 + 1] = w1;
            int p0 = atomicAdd(&g_cnt_v[e0], 1); g_list_v[e0 * T_ + p0] = t * 2 + 0;
            int p1 = atomicAdd(&g_cnt_v[e1], 1); g_list_v[e1 * T_ + p1] = t * 2 + 1;
        } else {
            g_wslot_o[t * 2 + 0] = w0;
            g_wslot_o[t * 2 + 1] = w1;
            int p0 = atomicAdd(&g_cnt_o[e0], 1); g_list_o[e0 * T_ + p0] = t * 2 + 0;
            int p1 = atomicAdd(&g_cnt_o[e1], 1); g_list_o[e1 * T_ + p1] = t * 2 + 1;
        }
    }
}

// ---------------- register-resident softmax ----------------
__global__ void softmax_kernel(const float* __restrict__ amask) {
    size_t row = blockIdx.x;
    int b = (int)(row / ((size_t)NH_ * S_));
    float* p = g_scores + row * S_;
    const float* mk = amask + (size_t)b * S_;
    int tid = threadIdx.x;
    int lane = tid & 31, wrp = tid >> 5;
    __shared__ float red[8];

    float v[8];
#pragma unroll
    for (int i = 0; i < 8; i++) {
        int k = tid + i * 256;
        v[i] = p[k] + (1.f - mk[k]) * (-10000.f);
    }
    float mx = v[0];
#pragma unroll
    for (int i = 1; i < 8; i++) mx = fmaxf(mx, v[i]);
#pragma unroll
    for (int o = 16; o > 0; o >>= 1) mx = fmaxf(mx, __shfl_xor_sync(0xffffffffu, mx, o));
    if (lane == 0) red[wrp] = mx;
    __syncthreads();
    float MX = red[0];
#pragma unroll
    for (int w = 1; w < 8; w++) MX = fmaxf(MX, red[w]);
    __syncthreads();

    float sum = 0.f;
#pragma unroll
    for (int i = 0; i < 8; i++) {
        v[i] = __expf(v[i] - MX);
        sum += v[i];
    }
#pragma unroll
    for (int o = 16; o > 0; o >>= 1) sum += __shfl_xor_sync(0xffffffffu, sum, o);
    if (lane == 0) red[wrp] = sum;
    __syncthreads();
    float SM = red[0];
#pragma unroll
    for (int w = 1; w < 8; w++) SM += red[w];
    float inv = 1.f / SM;
#pragma unroll
    for (int i = 0; i < 8; i++) p[tid + i * 256] = v[i] * inv;
}

// ---------------- launcher ----------------
extern "C" void kernel_launch(void* const* d_in, const int* in_sizes, int n_in,
                              void* d_out, int out_size) {
    const float* x      = (const float*)d_in[0];
    const float* amask  = (const float*)d_in[1];
    const float* wq     = (const float*)d_in[2];
    const float* wk     = (const float*)d_in[3];
    const float* q_a    = (const float*)d_in[4];
    const float* q_b    = (const float*)d_in[5];
    const float* k_a    = (const float*)d_in[6];
    const float* k_b    = (const float*)d_in[7];
    const float* gv     = (const float*)d_in[8];
    const float* go     = (const float*)d_in[9];
    const float* v_base = (const float*)d_in[10];
    const float* v_a    = (const float*)d_in[11];
    const float* v_b    = (const float*)d_in[12];
    const float* o_base = (const float*)d_in[13];
    const float* o_a    = (const float*)d_in[14];
    const float* o_b    = (const float*)d_in[15];
    float* out = (float*)d_out;

    void *p_q, *p_k, *p_vt, *p_ctx, *p_scores, *p_xacat, *p_xao, *p_wcat, *p_wcat2;
    void *p_list_v, *p_list_o, *p_cnt_v, *p_cnt_o, *p_ws_v, *p_ws_o;
    cudaGetSymbolAddress(&p_q, g_q);
    cudaGetSymbolAddress(&p_k, g_k);
    cudaGetSymbolAddress(&p_vt, g_vt);
    cudaGetSymbolAddress(&p_ctx, g_ctx);
    cudaGetSymbolAddress(&p_scores, g_scores);
    cudaGetSymbolAddress(&p_xacat, g_xacat);
    cudaGetSymbolAddress(&p_xao, g_xao);
    cudaGetSymbolAddress(&p_wcat, g_wcat);
    cudaGetSymbolAddress(&p_wcat2, g_wcat2);
    cudaGetSymbolAddress(&p_list_v, g_list_v);
    cudaGetSymbolAddress(&p_list_o, g_list_o);
    cudaGetSymbolAddress(&p_cnt_v, g_cnt_v);
    cudaGetSymbolAddress(&p_cnt_o, g_cnt_o);
    cudaGetSymbolAddress(&p_ws_v, g_wslot_v);
    cudaGetSymbolAddress(&p_ws_o, g_wslot_o);

    cudaFuncSetAttribute(tc_gemm<M_PROJ>,   cudaFuncAttributeMaxDynamicSharedMemorySize, SMEM_SZ);
    cudaFuncSetAttribute(tc_gemm<M_XA>,     cudaFuncAttributeMaxDynamicSharedMemorySize, SMEM_SZ);
    cudaFuncSetAttribute(tc_gemm<M_MOE>,    cudaFuncAttributeMaxDynamicSharedMemorySize, SMEM_SZ);
    cudaFuncSetAttribute(tc_gemm<M_MOEVT>,  cudaFuncAttributeMaxDynamicSharedMemorySize, SMEM_SZ);
    cudaFuncSetAttribute(tc_gemm<M_SCORES>, cudaFuncAttributeMaxDynamicSharedMemorySize, SMEM_SZ);
    cudaFuncSetAttribute(tc_gemm<M_CTX>,    cudaFuncAttributeMaxDynamicSharedMemorySize, SMEM_SZ);

    // assemble LoRA-A weight concats (contiguous D2D copies)
    cudaMemcpyAsync((float*)p_wcat,             q_a, sizeof(float) * R_ * H_,      cudaMemcpyDeviceToDevice);
    cudaMemcpyAsync((float*)p_wcat + 16 * H_,   k_a, sizeof(float) * R_ * H_,      cudaMemcpyDeviceToDevice);
    cudaMemcpyAsync((float*)p_wcat + 32 * H_,   v_a, sizeof(float) * E_ * R_ * H_, cudaMemcpyDeviceToDevice);
    cudaMemcpyAsync((float*)p_wcat2,            o_a, sizeof(float) * E_ * R_ * H_, cudaMemcpyDeviceToDevice);

    // reset per-replay state
    cudaMemsetAsync(p_vt, 0, sizeof(float) * (size_t)T_ * H_);
    cudaMemsetAsync(out, 0, sizeof(float) * (size_t)T_ * H_);
    init_counts_kernel<<<1, 32>>>();
    routing_kernel<<<T_, 128>>>(x, gv, go);

    // all LoRA-A down-projections in one tensor-core GEMM: xacat[T,128] = x @ wcat^T
    tc_gemm<M_XA><<<dim3(1, T_ / 128), 256, SMEM_SZ>>>(
        x, (const float*)p_wcat, (float*)p_xacat, nullptr, nullptr, nullptr, nullptr, nullptr);

    // Q / K projections (base + LoRA epilogue)
    tc_gemm<M_PROJ><<<dim3(H_ / 128, T_ / 128), 256, SMEM_SZ>>>(
        x, wq, (float*)p_q, (const float*)p_xacat + 0, q_b, nullptr, nullptr, nullptr);
    tc_gemm<M_PROJ><<<dim3(H_ / 128, T_ / 128), 256, SMEM_SZ>>>(
        x, wk, (float*)p_k, (const float*)p_xacat + 16, k_b, nullptr, nullptr, nullptr);

    // V MoE (gathered, top-2), writes TRANSPOSED g_vt
    tc_gemm<M_MOEVT><<<dim3(H_ / 128, T_ / 128, E_), 256, SMEM_SZ>>>(
        x, v_base, (float*)p_vt, (const float*)p_xacat + 32, v_b,
        (const int*)p_list_v, (const int*)p_cnt_v, (const float*)p_ws_v);

    // attention
    tc_gemm<M_SCORES><<<dim3(S_ / 128, S_ / 128, B_ * NH_), 256, SMEM_SZ>>>(
        (const float*)p_q, (const float*)p_k, (float*)p_scores,
        nullptr, nullptr, nullptr, nullptr, nullptr);
    softmax_kernel<<<(unsigned)((size_t)B_ * NH_ * S_), 256>>>(amask);
    tc_gemm<M_CTX><<<dim3(1, S_ / 128, B_ * NH_), 256, SMEM_SZ>>>(
        (const float*)p_scores, (const float*)p_vt, (float*)p_ctx,
        nullptr, nullptr, nullptr, nullptr, nullptr);

    // O-path LoRA down-projections + O MoE into final output
    tc_gemm<M_XA><<<dim3(1, T_ / 128), 256, SMEM_SZ>>>(
        (const float*)p_ctx, (const float*)p_wcat2, (float*)p_xao,
        nullptr, nullptr, nullptr, nullptr, nullptr);
    tc_gemm<M_MOE><<<dim3(H_ / 128, T_ / 128, E_), 256, SMEM_SZ>>>(
        (const float*)p_ctx, o_base, out, (const float*)p_xao, o_b,
        (const int*)p_list_o, (const int*)p_cnt_o, (const float*)p_ws_o);
}